// round 2
// baseline (speedup 1.0000x reference)
#include <cuda_runtime.h>
#include <cstdint>

#define NB 8
#define NC 256
#define NQ 4096
#define NK 4096
#define KNN 8

// Scratch (static __device__ globals — allocation-free per harness rules)
__device__ float g_KT[(size_t)NB * NK * NC];   // key_features transposed: (B, NK, C), 32MB
__device__ int   g_idx[(size_t)NB * NQ * KNN]; // knn indices, 1MB

// ---------------------------------------------------------------------------
// Kernel 1: transpose key_features (B,C,NK) -> g_KT (B,NK,C)
// ---------------------------------------------------------------------------
__global__ void transpose_kf(const float* __restrict__ kf) {
    __shared__ float t[32][33];
    int b  = blockIdx.z;
    int n0 = blockIdx.x * 32;
    int c0 = blockIdx.y * 32;
    int tx = threadIdx.x, ty0 = threadIdx.y;
#pragma unroll
    for (int dy = 0; dy < 32; dy += 8) {
        int ty = ty0 + dy;
        t[ty][tx] = kf[((size_t)b * NC + c0 + ty) * NK + n0 + tx];
    }
    __syncthreads();
#pragma unroll
    for (int dy = 0; dy < 32; dy += 8) {
        int ty = ty0 + dy;
        g_KT[((size_t)b * NK + n0 + ty) * NC + c0 + tx] = t[tx][ty];
    }
}

// ---------------------------------------------------------------------------
// Kernel 2: brute-force kNN, one thread per query, top-8 in registers.
// Distance computed to bit-match XLA's lowering of the reference:
//   qq  = rn(rn(rn(x*x)+rn(y*y))+rn(z*z))        (square+reduce, no fma)
//   dot = fma(q2,k2, fma(q1,k1, rn(q0*k0)))      (GEMM k-ascending fma chain)
//   d   = rn(rn(qq - 2*dot) + kk)                (source combine order; 2*dot exact)
// Tie-break: keys scanned ascending with strict '<' insert => stable lower-
// index-first among equals, matching jax.lax.top_k.
// ---------------------------------------------------------------------------
#define KCHUNK 2048
__global__ void knn_kernel(const float* __restrict__ qc,
                           const float* __restrict__ kc) {
    __shared__ float4 sk[KCHUNK];  // 32KB
    int b = blockIdx.y;
    int n = blockIdx.x * blockDim.x + threadIdx.x;

    const float* kb = kc + (size_t)b * 3 * NK;
    const float* qb = qc + (size_t)b * 3 * NQ;
    float qx = qb[n], qy = qb[NQ + n], qz = qb[2 * NQ + n];
    float qq = __fadd_rn(__fadd_rn(__fmul_rn(qx, qx), __fmul_rn(qy, qy)),
                         __fmul_rn(qz, qz));

    float bd[KNN];
    int   bi[KNN];
#pragma unroll
    for (int i = 0; i < KNN; i++) { bd[i] = 3.4e38f; bi[i] = 0; }

    for (int m0 = 0; m0 < NK; m0 += KCHUNK) {
        __syncthreads();
        for (int m = threadIdx.x; m < KCHUNK; m += blockDim.x) {
            float x = kb[m0 + m];
            float y = kb[NK + m0 + m];
            float z = kb[2 * NK + m0 + m];
            float kk = __fadd_rn(__fadd_rn(__fmul_rn(x, x), __fmul_rn(y, y)),
                                 __fmul_rn(z, z));
            sk[m] = make_float4(x, y, z, kk);
        }
        __syncthreads();
#pragma unroll 4
        for (int m = 0; m < KCHUNK; m++) {
            float4 k4 = sk[m];
            // dot = fma(qz*kz, fma(qy*ky, rn(qx*kx)))  (k ascending, acc from 0)
            float dot = __fmaf_rn(qz, k4.z,
                         __fmaf_rn(qy, k4.y, __fmul_rn(qx, k4.x)));
            float t = __fsub_rn(qq, 2.0f * dot);   // 2*dot exact (scale by 2)
            float d = __fadd_rn(t, k4.w);
            if (d < bd[KNN - 1]) {
                bd[KNN - 1] = d;
                bi[KNN - 1] = m0 + m;
#pragma unroll
                for (int j = KNN - 1; j > 0; j--) {
                    if (bd[j] < bd[j - 1]) {
                        float td = bd[j]; bd[j] = bd[j - 1]; bd[j - 1] = td;
                        int   ti = bi[j]; bi[j] = bi[j - 1]; bi[j - 1] = ti;
                    }
                }
            }
        }
    }
    int* o = g_idx + ((size_t)b * NQ + n) * KNN;
#pragma unroll
    for (int i = 0; i < KNN; i++) o[i] = bi[i];
}

// ---------------------------------------------------------------------------
// Kernel 3: gather + subtract + write, shared-memory staged for coalescing.
// CTA = (b, tile of 16 queries) = 128 (n,k) pairs. Channels in chunks of 64.
// out[b][c][n][k]     = KT[b][idx[n][k]][c] - qf[b][c][n]   (c in [0,256))
// out[b][c+256][n][k] = qf[b][c][n]
// ---------------------------------------------------------------------------
#define NT 16                    // queries per CTA
#define NP (NT * KNN)            // 128 (n,k) pairs
#define CCH 64                   // channel chunk

__global__ void gather_kernel(const float* __restrict__ qf,
                              float* __restrict__ out) {
    __shared__ float S[CCH][NP + 1];   // [c][p], pad to 129 -> conflict-free
    __shared__ float Qs[NT][CCH + 1];
    __shared__ int   sidx[NP];

    int b   = blockIdx.y;
    int n0  = blockIdx.x * NT;
    int tid = threadIdx.x;  // 256 threads

    if (tid < NP) sidx[tid] = g_idx[((size_t)b * NQ + n0) * KNN + tid];
    __syncthreads();

    const float* KTb = g_KT + (size_t)b * NK * NC;

    for (int c0 = 0; c0 < NC; c0 += CCH) {
        if (c0) __syncthreads();  // protect S/Qs reuse across chunks

        // Load gathered neighbor features: 128 pairs x 64 ch, float4 from KT.
        // 16 lanes cover one pair's 64 channels (256B contiguous read).
        for (int i = tid; i < NP * (CCH / 4); i += 256) {
            int p  = i >> 4;          // pair
            int c4 = (i & 15) * 4;    // channel quad
            float4 v = *reinterpret_cast<const float4*>(
                &KTb[(size_t)sidx[p] * NC + c0 + c4]);
            S[c4 + 0][p] = v.x;
            S[c4 + 1][p] = v.y;
            S[c4 + 2][p] = v.z;
            S[c4 + 3][p] = v.w;
        }
        // Load query features: 16 n x 64 ch (64B segments, coalesced enough).
        for (int i = tid; i < NT * CCH; i += 256) {
            int c = i >> 4, j = i & 15;
            Qs[j][c] = qf[((size_t)b * NC + c0 + c) * NQ + n0 + j];
        }
        __syncthreads();

        // Write: float4 along p (contiguous (n,k) axis) -> 512B/warp stores.
        for (int i = tid; i < CCH * (NP / 4); i += 256) {
            int c = i >> 5;            // channel within chunk
            int p = (i & 31) * 4;      // pair quad (all 4 share same n)
            float q = Qs[p >> 3][c];
            float4 d, qv;
            d.x = S[c][p + 0] - q;
            d.y = S[c][p + 1] - q;
            d.z = S[c][p + 2] - q;
            d.w = S[c][p + 3] - q;
            qv.x = q; qv.y = q; qv.z = q; qv.w = q;
            size_t ob = (((size_t)b * (2 * NC) + c0 + c) * NQ + n0) * KNN + p;
            *reinterpret_cast<float4*>(&out[ob]) = d;
            *reinterpret_cast<float4*>(&out[ob + (size_t)NC * NQ * KNN]) = qv;
        }
    }
}

// ---------------------------------------------------------------------------
extern "C" void kernel_launch(void* const* d_in, const int* in_sizes, int n_in,
                              void* d_out, int out_size) {
    const float* query_coords   = (const float*)d_in[0]; // (B,3,NQ)
    const float* query_features = (const float*)d_in[1]; // (B,C,NQ)
    const float* key_coords     = (const float*)d_in[2]; // (B,3,NK)
    const float* key_features   = (const float*)d_in[3]; // (B,C,NK)
    float* out = (float*)d_out;                          // (B,2C,NQ,K)

    // 1) transpose key_features -> (B,NK,C)
    {
        dim3 grid(NK / 32, NC / 32, NB);
        dim3 block(32, 8);
        transpose_kf<<<grid, block>>>(key_features);
    }
    // 2) kNN indices
    {
        dim3 grid(NQ / 128, NB);
        knn_kernel<<<grid, 128>>>(query_coords, key_coords);
    }
    // 3) gather + write
    {
        dim3 grid(NQ / NT, NB);
        gather_kernel<<<grid, 256>>>(query_features, out);
    }
}